// round 2
// baseline (speedup 1.0000x reference)
#include <cuda_runtime.h>
#include <math.h>

#define N_INST 16384
#define NB1    1024
#define NB2    64
#define DIM    1024
#define NATT   256
#define NCLS   512

// ---------------- scratch (device globals; no allocation allowed) ----------
__device__ float g_emb1[N_INST * DIM];   // 64 MB
__device__ float g_emb2[NB1 * DIM];      // 4 MB
__device__ float g_emb3[NB2 * DIM];
__device__ float g_s[N_INST + NB1 + NB2];
__device__ float g_stats[8];             // [max,sum] per level

__device__ __forceinline__ float* emb_buf(int lvl) {
    return lvl == 0 ? g_emb1 : (lvl == 1 ? g_emb2 : g_emb3);
}
__device__ __forceinline__ float* s_buf(int lvl) {
    return lvl == 0 ? g_s : (lvl == 1 ? g_s + N_INST : g_s + N_INST + NB1);
}

// ---------------------------------------------------------------------------
// Kernel 1: fused conv1+relu+pool -> conv2+relu+pool, one CTA per image.
//   conv1: 28x28x1 ->(5x5 VALID)-> 24x24x32 -> pool2 -> 12x12x32 (smem, stride-33 padded)
//   conv2: 12x12x32 ->(5x5 VALID)-> 8x8x64 -> pool2 -> 4x4x64 = emb1 row (1024)
// ---------------------------------------------------------------------------
#define P1_STRIDE 33   // pad to kill 16-way bank conflicts on position-major reads

__global__ __launch_bounds__(256) void fused_conv_kernel(
    const float* __restrict__ x,
    const float* __restrict__ w1, const float* __restrict__ b1,
    const float* __restrict__ w2, const float* __restrict__ b2)
{
    __shared__ float p1[144 * P1_STRIDE];  // 4752 floats: conv1 pooled output
    __shared__ float smu[6464];            // phaseA: in(784)+w1(800)+b1(32) | phaseB: w2 chunk(6400)+b2(64)

    const int tid = threadIdx.x;
    const int n   = blockIdx.x;

    // ---------------- Phase A: conv1 + relu + maxpool into smem ----------------
    {
        float* in_s = smu;          // 784
        float* w1_s = smu + 784;    // 800
        float* b1_s = smu + 1584;   // 32
        const float* xin = x + n * 784;
        for (int i = tid; i < 784; i += 256) in_s[i] = xin[i];
        for (int i = tid; i < 800; i += 256) w1_s[i] = w1[i];
        if (tid < 32) b1_s[tid] = b1[tid];
        __syncthreads();

        // 144 pooled positions x 8 channel-groups(of 4) = 1152 tasks
        for (int t = tid; t < 1152; t += 256) {
            const int c0 = (t & 7) * 4;
            const int p  = t >> 3;
            const int pr = p / 12, pc = p % 12;
            const int y0 = pr * 2, x0 = pc * 2;
            float acc[4][4];
            #pragma unroll
            for (int j = 0; j < 4; j++)
                #pragma unroll
                for (int ch = 0; ch < 4; ch++) acc[j][ch] = 0.f;

            for (int ky = 0; ky < 5; ky++) {
                #pragma unroll
                for (int kx = 0; kx < 5; kx++) {
                    const float4 wv = *(const float4*)&w1_s[(ky * 5 + kx) * 32 + c0];
                    #pragma unroll
                    for (int j = 0; j < 4; j++) {
                        const int dy = j >> 1, dx = j & 1;
                        const float iv = in_s[(y0 + dy + ky) * 28 + (x0 + dx + kx)];
                        acc[j][0] += iv * wv.x; acc[j][1] += iv * wv.y;
                        acc[j][2] += iv * wv.z; acc[j][3] += iv * wv.w;
                    }
                }
            }
            #pragma unroll
            for (int ch = 0; ch < 4; ch++) {
                float m = fmaxf(fmaxf(acc[0][ch], acc[1][ch]), fmaxf(acc[2][ch], acc[3][ch]));
                p1[p * P1_STRIDE + c0 + ch] = fmaxf(m + b1_s[c0 + ch], 0.f);
            }
        }
    }
    __syncthreads();

    // ---------------- Phase B: conv2 + relu + maxpool -> emb1 ----------------
    {
        float* w2_s = smu;          // 6400 per ci-chunk: [(ky*5+kx)*256 + cil*64 + c]
        float* b2_s = smu + 6400;   // 64

        const int c0 = (tid & 15) * 4;   // 16 groups x 4 out-channels = 64
        const int p  = tid >> 4;         // 16 pooled positions
        const int pr = p >> 2, pc = p & 3;
        const int y0 = pr * 2, x0 = pc * 2;

        float acc[4][4];
        #pragma unroll
        for (int j = 0; j < 4; j++)
            #pragma unroll
            for (int ch = 0; ch < 4; ch++) acc[j][ch] = 0.f;

        for (int cc = 0; cc < 8; cc++) {   // 8 chunks of 4 input channels
            __syncthreads();               // previous chunk consumed
            for (int i = tid; i < 6400; i += 256) {
                const int q = i >> 8;      // ky*5+kx
                const int r = i & 255;     // cil*64 + c
                w2_s[i] = w2[q * 2048 + cc * 256 + r];
            }
            if (cc == 0 && tid < 64) b2_s[tid] = b2[tid];
            __syncthreads();

            for (int ky = 0; ky < 5; ky++) {
                #pragma unroll
                for (int kx = 0; kx < 5; kx++) {
                    const int wbase = (ky * 5 + kx) * 256;
                    #pragma unroll
                    for (int cil = 0; cil < 4; cil++) {
                        const int ci = cc * 4 + cil;
                        const float4 wv = *(const float4*)&w2_s[wbase + cil * 64 + c0];
                        #pragma unroll
                        for (int j = 0; j < 4; j++) {
                            const int dy = j >> 1, dx = j & 1;
                            const float iv =
                                p1[((y0 + dy + ky) * 12 + (x0 + dx + kx)) * P1_STRIDE + ci];
                            acc[j][0] += iv * wv.x; acc[j][1] += iv * wv.y;
                            acc[j][2] += iv * wv.z; acc[j][3] += iv * wv.w;
                        }
                    }
                }
            }
        }

        float4 o;
        float* op = &o.x;
        #pragma unroll
        for (int ch = 0; ch < 4; ch++) {
            float m = fmaxf(fmaxf(acc[0][ch], acc[1][ch]), fmaxf(acc[2][ch], acc[3][ch]));
            op[ch] = fmaxf(m + b2_s[c0 + ch], 0.f);
        }
        *(float4*)&g_emb1[n * DIM + p * 64 + c0] = o;
    }
}

// ---------------------------------------------------------------------------
// Kernel 2: attention scores s_i = sigmoid(tanh(emb_i @ W + b) @ v + vb)
// 8 rows per CTA staged in smem; 256 threads = 256 attention units.
// ---------------------------------------------------------------------------
__global__ __launch_bounds__(256) void att_kernel(
    int lvl, const float* __restrict__ W, const float* __restrict__ b,
    const float* __restrict__ v, const float* __restrict__ vb)
{
    __shared__ float es[8 * DIM];      // 32 KB
    __shared__ float wred[8][8];

    const float* emb   = emb_buf(lvl);
    float*       s_out = s_buf(lvl);
    const int tid  = threadIdx.x;
    const int row0 = blockIdx.x * 8;

    const float* src = emb + (long)row0 * DIM;
    for (int i = tid; i < 8 * DIM; i += 256) es[i] = src[i];
    __syncthreads();

    float acc[8] = {0.f, 0.f, 0.f, 0.f, 0.f, 0.f, 0.f, 0.f};
    const float* Wp = W + tid;
    for (int k = 0; k < DIM; k += 4) {
        const float wv0 = Wp[(k + 0) * NATT];
        const float wv1 = Wp[(k + 1) * NATT];
        const float wv2 = Wp[(k + 2) * NATT];
        const float wv3 = Wp[(k + 3) * NATT];
        #pragma unroll
        for (int r = 0; r < 8; r++) {
            const float4 e = *(const float4*)&es[r * DIM + k];
            acc[r] += e.x * wv0;
            acc[r] += e.y * wv1;
            acc[r] += e.z * wv2;
            acc[r] += e.w * wv3;
        }
    }

    const float bj = b[tid], vj = v[tid];
    const int lane = tid & 31, wrp = tid >> 5;
    #pragma unroll
    for (int r = 0; r < 8; r++) {
        float pv = tanhf(acc[r] + bj) * vj;
        #pragma unroll
        for (int off = 16; off; off >>= 1) pv += __shfl_xor_sync(0xffffffffu, pv, off);
        if (lane == 0) wred[wrp][r] = pv;
    }
    __syncthreads();
    if (tid < 8) {
        float z = 0.f;
        #pragma unroll
        for (int w = 0; w < 8; w++) z += wred[w][tid];
        z += vb[0];
        s_out[row0 + tid] = 1.f / (1.f + expf(-z));
    }
}

// ---------------------------------------------------------------------------
// Kernel 3: global softmax stats (max, sum of exp)
// ---------------------------------------------------------------------------
__global__ __launch_bounds__(1024) void stats_kernel(int lvl, int R)
{
    __shared__ float red[1024];
    const float* s = s_buf(lvl);
    const int tid = threadIdx.x;

    float m = -1e30f;
    for (int i = tid; i < R; i += 1024) m = fmaxf(m, s[i]);
    red[tid] = m; __syncthreads();
    for (int off = 512; off; off >>= 1) {
        if (tid < off) red[tid] = fmaxf(red[tid], red[tid + off]);
        __syncthreads();
    }
    const float mx = red[0];
    __syncthreads();

    float sum = 0.f;
    for (int i = tid; i < R; i += 1024) sum += expf(s[i] - mx);
    red[tid] = sum; __syncthreads();
    for (int off = 512; off; off >>= 1) {
        if (tid < off) red[tid] += red[tid + off];
        __syncthreads();
    }
    if (tid == 0) { g_stats[lvl * 2] = mx; g_stats[lvl * 2 + 1] = red[0]; }
}

// ---------------------------------------------------------------------------
// Kernel 4: softmax-weighted segment sum (16 contiguous rows per bag)
// ---------------------------------------------------------------------------
__global__ __launch_bounds__(256) void segsum_kernel(int lvl)
{
    __shared__ float ws[16];
    const float* ein  = emb_buf(lvl);
    float*       eout = emb_buf(lvl + 1);
    const float* s    = s_buf(lvl);
    const int bg = blockIdx.x, tid = threadIdx.x;

    if (tid < 16) {
        const float mx = g_stats[lvl * 2];
        const float inv = 1.f / g_stats[lvl * 2 + 1];
        ws[tid] = expf(s[bg * 16 + tid] - mx) * inv;
    }
    __syncthreads();

    const float* base = ein + (long)bg * 16 * DIM;
    for (int d = tid; d < DIM; d += 256) {
        float acc = 0.f;
        #pragma unroll
        for (int i = 0; i < 16; i++) acc += ws[i] * base[i * DIM + d];
        eout[bg * DIM + d] = acc;
    }
}

// ---------------------------------------------------------------------------
// Kernel 5: level-3 softmax + outer pooling + classifier + sigmoid
// ---------------------------------------------------------------------------
__global__ __launch_bounds__(512) void final_kernel(
    const float* __restrict__ clsW, const float* __restrict__ clsb,
    const float* __restrict__ outW, const float* __restrict__ outb,
    float* __restrict__ out)
{
    __shared__ float w3[64];
    __shared__ float outer[DIM];
    __shared__ float red[512];
    const int tid = threadIdx.x;
    const float* s3 = s_buf(2);

    if (tid == 0) {
        float mx = -1e30f;
        for (int i = 0; i < 64; i++) mx = fmaxf(mx, s3[i]);
        float sum = 0.f;
        for (int i = 0; i < 64; i++) { float e = expf(s3[i] - mx); w3[i] = e; sum += e; }
        const float inv = 1.f / sum;
        for (int i = 0; i < 64; i++) w3[i] *= inv;
    }
    __syncthreads();

    for (int d = tid; d < DIM; d += 512) {
        float acc = 0.f;
        #pragma unroll 8
        for (int b2 = 0; b2 < 64; b2++) acc += w3[b2] * g_emb3[b2 * DIM + d];
        outer[d] = acc;
    }
    __syncthreads();

    float acc = 0.f;
    const float* wp = clsW + tid;
    for (int d = 0; d < DIM; d++) acc += outer[d] * wp[d * NCLS];
    red[tid] = (acc + clsb[tid]) * outW[tid];
    __syncthreads();
    for (int off = 256; off; off >>= 1) {
        if (tid < off) red[tid] += red[tid + off];
        __syncthreads();
    }
    if (tid == 0) out[0] = 1.f / (1.f + expf(-(red[0] + outb[0])));
}

// ---------------------------------------------------------------------------
extern "C" void kernel_launch(void* const* d_in, const int* in_sizes, int n_in,
                              void* d_out, int out_size)
{
    const float* x    = (const float*)d_in[0];
    const float* c1w  = (const float*)d_in[1];
    const float* c1b  = (const float*)d_in[2];
    const float* c2w  = (const float*)d_in[3];
    const float* c2b  = (const float*)d_in[4];
    const float* a1W  = (const float*)d_in[5];
    const float* a1b  = (const float*)d_in[6];
    const float* a1v  = (const float*)d_in[7];
    const float* a1vb = (const float*)d_in[8];
    const float* a2W  = (const float*)d_in[9];
    const float* a2b  = (const float*)d_in[10];
    const float* a2v  = (const float*)d_in[11];
    const float* a2vb = (const float*)d_in[12];
    const float* a3W  = (const float*)d_in[13];
    const float* a3b  = (const float*)d_in[14];
    const float* a3v  = (const float*)d_in[15];
    const float* a3vb = (const float*)d_in[16];
    const float* clsW = (const float*)d_in[17];
    const float* clsb = (const float*)d_in[18];
    const float* outW = (const float*)d_in[19];
    const float* outb = (const float*)d_in[20];

    fused_conv_kernel<<<N_INST, 256>>>(x, c1w, c1b, c2w, c2b);

    att_kernel<<<N_INST / 8, 256>>>(0, a1W, a1b, a1v, a1vb);
    stats_kernel<<<1, 1024>>>(0, N_INST);
    segsum_kernel<<<NB1, 256>>>(0);

    att_kernel<<<NB1 / 8, 256>>>(1, a2W, a2b, a2v, a2vb);
    stats_kernel<<<1, 1024>>>(1, NB1);
    segsum_kernel<<<NB2, 256>>>(1);

    att_kernel<<<NB2 / 8, 256>>>(2, a3W, a3b, a3v, a3vb);
    final_kernel<<<1, 512>>>(clsW, clsb, outW, outb, (float*)d_out);
}